// round 12
// baseline (speedup 1.0000x reference)
// R11: gemm_mma -> 4-stage cp.async pipeline, K-chunk 16, 96KB smem (2 CTA/SM).
// Launch order set so ncu (-s 5 = my idx 3 after 2 harness launches) profiles gemm1.
// Flash (HMMA, R9) unchanged. Best: R10 = 1559.2us.
#include <cuda_runtime.h>
#include <cuda_bf16.h>
#include <math.h>
#include <stdint.h>

#define SEQ    2048
#define DM     2048
#define NHEAD  16
#define QLORA  1536
#define KVLORA 512
#define ROPED  64
#define NOPED  128
#define VD     128
#define QHDIM  192
#define KVW    576
#define KVROW  256
#define MASKW  2198
#define NEG_BIG (-1e30f)

#define NQ   (NHEAD * QHDIM)   // 3072
#define NKV  (NHEAD * KVROW)   // 4096
#define KVWP 640

// ---------------- fp32 scratch ----------------
__device__ float g_qlat[SEQ * QLORA];
__device__ float g_ckv [SEQ * KVW];
__device__ float g_q   [SEQ * NQ];
__device__ float g_kv  [SEQ * NKV];
__device__ float g_ao  [SEQ * DM];

// ---------------- bf16 hi/lo split buffers ----------------
__device__ unsigned short g_xh [SEQ * DM],    g_xl [SEQ * DM];
__device__ unsigned short g_qlh[SEQ * QLORA], g_qll[SEQ * QLORA];
__device__ unsigned short g_ckh[SEQ * KVW],   g_ckl[SEQ * KVW];
__device__ unsigned short g_aoh[SEQ * DM],    g_aol[SEQ * DM];
__device__ unsigned short g_WqaTh [QLORA * DM],  g_WqaTl [QLORA * DM];
__device__ unsigned short g_WkvaTh[KVWP  * DM],  g_WkvaTl[KVWP  * DM];
__device__ unsigned short g_WqbTh [NQ * QLORA],  g_WqbTl [NQ * QLORA];
__device__ unsigned short g_WkvbTh[NKV * KVLORA],g_WkvbTl[NKV * KVLORA];
__device__ unsigned short g_WoTh  [DM * DM],     g_WoTl  [DM * DM];
__device__ unsigned short g_Qbh[NHEAD * SEQ * QHDIM], g_Qbl[NHEAD * SEQ * QHDIM];
__device__ unsigned short g_Kbh[NHEAD * SEQ * QHDIM], g_Kbl[NHEAD * SEQ * QHDIM];
__device__ unsigned short g_Vbh[NHEAD * SEQ * VD],    g_Vbl[NHEAD * SEQ * VD];

// ======================= PTX helpers =======================
__device__ __forceinline__ uint32_t smem_u32(const void* p) {
    uint32_t a;
    asm("{ .reg .u64 t; cvta.to.shared.u64 t, %1; cvt.u32.u64 %0, t; }"
        : "=r"(a) : "l"(p));
    return a;
}
__device__ __forceinline__ void ldm_x4(uint32_t* r, uint32_t a) {
    asm volatile("ldmatrix.sync.aligned.m8n8.x4.shared.b16 {%0,%1,%2,%3}, [%4];"
        : "=r"(r[0]), "=r"(r[1]), "=r"(r[2]), "=r"(r[3]) : "r"(a));
}
__device__ __forceinline__ void ldm_x4_t(uint32_t* r, uint32_t a) {
    asm volatile("ldmatrix.sync.aligned.m8n8.x4.trans.shared.b16 {%0,%1,%2,%3}, [%4];"
        : "=r"(r[0]), "=r"(r[1]), "=r"(r[2]), "=r"(r[3]) : "r"(a));
}
__device__ __forceinline__ void mma16816(float* c, const uint32_t* a, const uint32_t* b) {
    asm volatile(
        "mma.sync.aligned.m16n8k16.row.col.f32.bf16.bf16.f32 "
        "{%0,%1,%2,%3}, {%4,%5,%6,%7}, {%8,%9}, {%0,%1,%2,%3};"
        : "+f"(c[0]), "+f"(c[1]), "+f"(c[2]), "+f"(c[3])
        : "r"(a[0]), "r"(a[1]), "r"(a[2]), "r"(a[3]), "r"(b[0]), "r"(b[1]));
}
__device__ __forceinline__ void cp16(uint32_t dst, const void* src) {
    asm volatile("cp.async.cg.shared.global [%0], [%1], 16;" :: "r"(dst), "l"(src));
}
#define CP_COMMIT() asm volatile("cp.async.commit_group;" ::: "memory")
#define CP_WAIT3()  asm volatile("cp.async.wait_group 3;" ::: "memory")

__device__ __forceinline__ void bsplit(float v, unsigned short& h, unsigned short& l) {
    __nv_bfloat16 bh = __float2bfloat16(v);
    __nv_bfloat16 bl = __float2bfloat16(v - __bfloat162float(bh));
    h = __bfloat16_as_ushort(bh);
    l = __bfloat16_as_ushort(bl);
}
__device__ __forceinline__ void hl_pack(float x, float y, uint32_t& hr, uint32_t& lr) {
    __nv_bfloat16 xh = __float2bfloat16(x);
    __nv_bfloat16 yh = __float2bfloat16(y);
    __nv_bfloat16 xl = __float2bfloat16(x - __bfloat162float(xh));
    __nv_bfloat16 yl = __float2bfloat16(y - __bfloat162float(yh));
    hr = (uint32_t)__bfloat16_as_ushort(xh) | ((uint32_t)__bfloat16_as_ushort(yh) << 16);
    lr = (uint32_t)__bfloat16_as_ushort(xl) | ((uint32_t)__bfloat16_as_ushort(yl) << 16);
}

// ======================= prep kernels =======================
__global__ void __launch_bounds__(256) split2(
    const float* __restrict__ src, unsigned short* __restrict__ h,
    unsigned short* __restrict__ l, int n)
{
    int i = blockIdx.x * 256 + threadIdx.x;
    if (i < n) bsplit(src[i], h[i], l[i]);
}

__global__ void __launch_bounds__(256) transpose_split(
    const float* __restrict__ W, unsigned short* __restrict__ Th,
    unsigned short* __restrict__ Tl, int K, int N)
{
    __shared__ float t[32][33];
    int n0 = blockIdx.x * 32, k0 = blockIdx.y * 32;
    int tx = threadIdx.x & 31, ty = threadIdx.x >> 5;
    #pragma unroll
    for (int i = 0; i < 4; i++) {
        int k = k0 + ty + i * 8, n = n0 + tx;
        t[ty + i * 8][tx] = (n < N) ? W[(size_t)k * N + n] : 0.f;
    }
    __syncthreads();
    #pragma unroll
    for (int i = 0; i < 4; i++) {
        int n = n0 + ty + i * 8, k = k0 + tx;
        bsplit(t[tx][ty + i * 8], Th[(size_t)n * K + k], Tl[(size_t)n * K + k]);
    }
}

// ================= HMMA split GEMM, 4-stage cp.async, K-chunk 16 ==========
// smem tile row: 16 bf16 (32B) + 16B pad = 48B stride. Stage = 4 tensors x 6KB.
#define T_STRIDE_US 24
#define TEN_US      (128 * 24)      // 3072 us = 6144 B per tensor tile
#define STAGE_US    (4 * TEN_US)    // 12288 us = 24576 B
#define GEMM_SMEM   (4 * STAGE_US * 2)   // 98304 B

__global__ void __launch_bounds__(256) gemm_mma(
    const unsigned short* __restrict__ Ahp, const unsigned short* __restrict__ Alp, int lda,
    const unsigned short* __restrict__ Bhp, const unsigned short* __restrict__ Blp, int ldb,
    float* __restrict__ C, int ldc, int N, int K)
{
    extern __shared__ unsigned short smus[];
    const uint32_t sbase = smem_u32(smus);
    const int tid  = threadIdx.x;
    const int lane = tid & 31;
    const int wid  = tid >> 5;
    const int wm   = wid & 1;
    const int wn   = wid >> 1;
    const int row0 = blockIdx.y * 128;
    const int col0 = blockIdx.x * 128;

    const unsigned short* bases[4] = { Ahp, Alp, Bhp, Blp };
    const int ldv[4] = { lda, lda, ldb, ldb };
    const int rbv[4] = { row0, row0, col0, col0 };

    float acc[4][4][4];
    #pragma unroll
    for (int i = 0; i < 4; i++)
        #pragma unroll
        for (int j = 0; j < 4; j++)
            #pragma unroll
            for (int q = 0; q < 4; q++) acc[i][j][q] = 0.f;

    const int NC = K >> 4;             // 16-wide K chunks

    // ldmatrix addresses (48B row stride)
    const uint32_t aoff = (uint32_t)((wm * 64 + (lane & 15)) * 48 + (lane >> 4) * 16);
    const uint32_t boff = (uint32_t)((wn * 32 + ((lane >> 4) * 8) + (lane & 7)) * 48
                                     + (((lane >> 3) & 1) * 16));

    // copy mapping: 4 x 16B per thread covers 4 tensors x 128 rows x 32B
    auto issue_chunk = [&](int c, int s) {
        const int k0 = c << 4;
        const uint32_t sb = sbase + (uint32_t)s * (STAGE_US * 2);
        #pragma unroll
        for (int i = 0; i < 4; i++) {
            int w = tid + i * 256;     // 0..1023
            int t = w >> 8;            // tensor
            int v = w & 255;
            int r = v >> 1, cc = v & 1;
            cp16(sb + (uint32_t)(t * TEN_US + r * T_STRIDE_US + cc * 8) * 2,
                 bases[t] + (size_t)(rbv[t] + r) * ldv[t] + k0 + cc * 8);
        }
        CP_COMMIT();
    };

    issue_chunk(0, 0);
    issue_chunk(1, 1);
    issue_chunk(2, 2);

    for (int c = 0; c < NC; c++) {
        const int s = c & 3;
        if (c + 3 < NC) issue_chunk(c + 3, (c + 3) & 3);
        else            CP_COMMIT();          // empty group keeps wait count uniform
        CP_WAIT3();                            // chunk c resident
        __syncthreads();

        const uint32_t st = sbase + (uint32_t)s * (STAGE_US * 2);
        uint32_t Ah[4][4], Al[4][4], Bh[4][2], Bl[4][2];
        #pragma unroll
        for (int mf = 0; mf < 4; mf++) {
            ldm_x4(Ah[mf], st + 0          + aoff + (uint32_t)(mf * 16 * 48));
            ldm_x4(Al[mf], st + TEN_US * 2 + aoff + (uint32_t)(mf * 16 * 48));
        }
        #pragma unroll
        for (int np = 0; np < 2; np++) {
            uint32_t rh[4], rl[4];
            ldm_x4(rh, st + TEN_US * 4 + boff + (uint32_t)(np * 16 * 48));
            ldm_x4(rl, st + TEN_US * 6 + boff + (uint32_t)(np * 16 * 48));
            Bh[np * 2][0] = rh[0]; Bh[np * 2][1] = rh[1];
            Bh[np * 2 + 1][0] = rh[2]; Bh[np * 2 + 1][1] = rh[3];
            Bl[np * 2][0] = rl[0]; Bl[np * 2][1] = rl[1];
            Bl[np * 2 + 1][0] = rl[2]; Bl[np * 2 + 1][1] = rl[3];
        }
        #pragma unroll
        for (int mf = 0; mf < 4; mf++)
            #pragma unroll
            for (int nf = 0; nf < 4; nf++) {
                mma16816(acc[mf][nf], Ah[mf], Bh[nf]);
                mma16816(acc[mf][nf], Ah[mf], Bl[nf]);
                mma16816(acc[mf][nf], Al[mf], Bh[nf]);
            }
        __syncthreads();
    }

    #pragma unroll
    for (int mf = 0; mf < 4; mf++) {
        int r0 = row0 + wm * 64 + mf * 16 + (lane >> 2);
        #pragma unroll
        for (int nf = 0; nf < 4; nf++) {
            int c0 = col0 + wn * 32 + nf * 8 + (lane & 3) * 2;
            if (c0 < N) {
                C[(size_t)r0 * ldc + c0] = acc[mf][nf][0];
                C[(size_t)(r0 + 8) * ldc + c0] = acc[mf][nf][2];
            }
            if (c0 + 1 < N) {
                C[(size_t)r0 * ldc + c0 + 1] = acc[mf][nf][1];
                C[(size_t)(r0 + 8) * ldc + c0 + 1] = acc[mf][nf][3];
            }
        }
    }
}

// ======================= rmsnorm =======================
__global__ void __launch_bounds__(256) rmsnorm_kernel(
    float* __restrict__ data, const float* __restrict__ w, int W, int ld)
{
    const int row = blockIdx.x;
    float* p = data + (size_t)row * ld;
    float ss = 0.f;
    for (int c = threadIdx.x; c < W; c += 256) { float v = p[c]; ss += v * v; }
    __shared__ float red[256];
    red[threadIdx.x] = ss;
    __syncthreads();
    #pragma unroll
    for (int s = 128; s > 0; s >>= 1) {
        if (threadIdx.x < s) red[threadIdx.x] += red[threadIdx.x + s];
        __syncthreads();
    }
    float scale = rsqrtf(red[0] / (float)W + 1e-6f);
    for (int c = threadIdx.x; c < W; c += 256) p[c] = w[c] * (p[c] * scale);
}

// ======================= rope + per-head bf16 hi/lo layout =================
__global__ void __launch_bounds__(256) build_qk(const float* __restrict__ freqs)
{
    const int s = blockIdx.x;
    const int tid = threadIdx.x;
    __shared__ float cs[32], sn[32];
    if (tid < 32) {
        cs[tid] = freqs[(s * 32 + tid) * 2 + 0];
        sn[tid] = freqs[(s * 32 + tid) * 2 + 1];
    }
    __syncthreads();

    const float* qrow = g_q + (size_t)s * NQ;
    for (int idx = tid; idx < NQ; idx += 256) {
        int hh = idx / QHDIM, d = idx % QHDIM;
        float val;
        if (d < ROPED) {
            int j = d >> 1;
            float a = qrow[hh * QHDIM + NOPED + 2 * j];
            float b = qrow[hh * QHDIM + NOPED + 2 * j + 1];
            val = (d & 1) ? (a * sn[j] + b * cs[j]) : (a * cs[j] - b * sn[j]);
        } else {
            val = qrow[hh * QHDIM + (d - ROPED)];
        }
        size_t off = ((size_t)hh * SEQ + s) * QHDIM + d;
        bsplit(val, g_Qbh[off], g_Qbl[off]);
    }

    const float* kperow = g_ckv + (size_t)s * KVW + KVLORA;
    const float* kvrow  = g_kv  + (size_t)s * NKV;
    for (int idx = tid; idx < NQ; idx += 256) {
        int hh = idx / QHDIM, d = idx % QHDIM;
        float val;
        if (d < ROPED) {
            int j = d >> 1;
            float a = kperow[2 * j], b = kperow[2 * j + 1];
            val = (d & 1) ? (a * sn[j] + b * cs[j]) : (a * cs[j] - b * sn[j]);
        } else {
            val = kvrow[hh * KVROW + (d - ROPED)];
        }
        size_t off = ((size_t)hh * SEQ + s) * QHDIM + d;
        bsplit(val, g_Kbh[off], g_Kbl[off]);
    }

    for (int idx = tid; idx < NHEAD * VD; idx += 256) {
        int hh = idx / VD, d = idx % VD;
        float v = kvrow[hh * KVROW + NOPED + d];
        size_t off = ((size_t)hh * SEQ + s) * VD + d;
        bsplit(v, g_Vbh[off], g_Vbl[off]);
    }
}

// ======================= HMMA flash attention (unchanged R9) ==============
#define FL_SMEM_BYTES 188416

__global__ void __launch_bounds__(256) flash_mma(
    const int* __restrict__ mask, float* __restrict__ ao)
{
    extern __shared__ unsigned short fsm[];
    const uint32_t sb = smem_u32(fsm);
    const int tid  = threadIdx.x;
    const int lane = tid & 31;
    const int wq   = tid >> 5;
    const int qb   = blockIdx.x;
    const int h    = blockIdx.y;
    const int g    = lane >> 2;
    const int t    = lane & 3;
    const int bq   = lane >> 3;
    const int br   = lane & 7;
    const float scale = 0.088388347648318447f;

    unsigned short* Qh_s = fsm;
    unsigned short* Ql_s = fsm + 25600;
    unsigned short* Kh_s = fsm + 51200;
    unsigned short* Kl_s = fsm + 64000;
    unsigned short* Vh_s = fsm + 76800;
    unsigned short* Vl_s = fsm + 85504;

    const uint32_t aH = sb + (uint32_t)((wq * 16 + (lane & 15)) * 400 + (lane >> 4) * 16);
    const uint32_t aL = aH + 51200;
    const uint32_t kH = sb + 102400 + (uint32_t)(((bq >> 1) * 8 + br) * 400 + (bq & 1) * 16);
    const uint32_t kL = kH + 25600;
    const uint32_t vH = sb + 153600 + (uint32_t)(((bq & 1) * 8 + br) * 272 + (bq >> 1) * 16);
    const uint32_t vL = vH + 17408;

    const size_t qgo = ((size_t)h * SEQ + (size_t)qb * 128) * QHDIM;
    for (int i = tid; i < 128 * 24; i += 256) {
        int r = i / 24, c = i % 24;
        *(uint4*)(Qh_s + r * 200 + c * 8) = *(const uint4*)(g_Qbh + qgo + (size_t)r * QHDIM + c * 8);
        *(uint4*)(Ql_s + r * 200 + c * 8) = *(const uint4*)(g_Qbl + qgo + (size_t)r * QHDIM + c * 8);
    }

    float o[16][4];
    #pragma unroll
    for (int i = 0; i < 16; i++)
        #pragma unroll
        for (int j = 0; j < 4; j++) o[i][j] = 0.f;
    float mr0 = NEG_BIG, mr1 = NEG_BIG, l0 = 0.f, l1 = 0.f;

    const int row0g = qb * 128 + wq * 16 + g;

    for (int kb = 0; kb < SEQ / 64; kb++) {
        __syncthreads();
        const size_t kgo = ((size_t)h * SEQ + (size_t)kb * 64) * QHDIM;
        for (int i = tid; i < 64 * 24; i += 256) {
            int r = i / 24, c = i % 24;
            *(uint4*)(Kh_s + r * 200 + c * 8) = *(const uint4*)(g_Kbh + kgo + (size_t)r * QHDIM + c * 8);
            *(uint4*)(Kl_s + r * 200 + c * 8) = *(const uint4*)(g_Kbl + kgo + (size_t)r * QHDIM + c * 8);
        }
        const size_t vgo = ((size_t)h * SEQ + (size_t)kb * 64) * VD;
        for (int i = tid; i < 64 * 16; i += 256) {
            int r = i / 16, c = i % 16;
            *(uint4*)(Vh_s + r * 136 + c * 8) = *(const uint4*)(g_Vbh + vgo + (size_t)r * VD + c * 8);
            *(uint4*)(Vl_s + r * 136 + c * 8) = *(const uint4*)(g_Vbl + vgo + (size_t)r * VD + c * 8);
        }
        __syncthreads();

        float s[8][4];
        #pragma unroll
        for (int f = 0; f < 8; f++)
            #pragma unroll
            for (int e = 0; e < 4; e++) s[f][e] = 0.f;

        #pragma unroll
        for (int kk = 0; kk < 12; kk++) {
            uint32_t ah[4], al[4];
            ldm_x4(ah, aH + kk * 32);
            ldm_x4(al, aL + kk * 32);
            #pragma unroll
            for (int np = 0; np < 4; np++) {
                uint32_t bh[4], bl[4];
                ldm_x4(bh, kH + np * (16 * 400) + kk * 32);
                ldm_x4(bl, kL + np * (16 * 400) + kk * 32);
                mma16816(s[2 * np],     ah, bh);
                mma16816(s[2 * np],     ah, bl);
                mma16816(s[2 * np],     al, bh);
                mma16816(s[2 * np + 1], ah, bh + 2);
                mma16816(s[2 * np + 1], ah, bl + 2);
                mma16816(s[2 * np + 1], al, bh + 2);
            }
        }

        #pragma unroll
        for (int f = 0; f < 8; f++)
            #pragma unroll
            for (int e = 0; e < 4; e++) s[f][e] *= scale;

        const int colbase = 150 + kb * 64;
        #pragma unroll
        for (int f = 0; f < 8; f++) {
            int col = colbase + f * 8 + 2 * t;
            int2 m0v = *(const int2*)(mask + (size_t)row0g * MASKW + col);
            int2 m1v = *(const int2*)(mask + (size_t)(row0g + 8) * MASKW + col);
            if (m0v.x == 1) s[f][0] = NEG_BIG;
            if (m0v.y == 1) s[f][1] = NEG_BIG;
            if (m1v.x == 1) s[f][2] = NEG_BIG;
            if (m1v.y == 1) s[f][3] = NEG_BIG;
        }

        float m0 = NEG_BIG, m1 = NEG_BIG;
        #pragma unroll
        for (int f = 0; f < 8; f++) {
            m0 = fmaxf(m0, fmaxf(s[f][0], s[f][1]));
            m1 = fmaxf(m1, fmaxf(s[f][2], s[f][3]));
        }
        m0 = fmaxf(m0, __shfl_xor_sync(0xffffffffu, m0, 1));
        m0 = fmaxf(m0, __shfl_xor_sync(0xffffffffu, m0, 2));
        m1 = fmaxf(m1, __shfl_xor_sync(0xffffffffu, m1, 1));
        m1 = fmaxf(m1, __shfl_xor_sync(0xffffffffu, m1, 2));
        float nm0 = fmaxf(mr0, m0), nm1 = fmaxf(mr1, m1);
        float al0 = __expf(mr0 - nm0), al1 = __expf(mr1 - nm1);
        mr0 = nm0; mr1 = nm1;

        float sum0 = 0.f, sum1 = 0.f;
        #pragma unroll
        for (int f = 0; f < 8; f++) {
            s[f][0] = __expf(s[f][0] - nm0);
            s[f][1] = __expf(s[f][1] - nm0);
            s[f][2] = __expf(s[f][2] - nm1);
            s[f][3] = __expf(s[f][3] - nm1);
            sum0 += s[f][0] + s[f][1];
            sum1 += s[f][2] + s[f][3];
        }
        sum0 += __shfl_xor_sync(0xffffffffu, sum0, 1);
        sum0 += __shfl_xor_sync(0xffffffffu, sum0, 2);
        sum1 += __shfl_xor_sync(0xffffffffu, sum1, 1);
        sum1 += __shfl_xor_sync(0xffffffffu, sum1, 2);
        l0 = l0 * al0 + sum0;
        l1 = l1 * al1 + sum1;

        #pragma unroll
        for (int nf = 0; nf < 16; nf++) {
            o[nf][0] *= al0; o[nf][1] *= al0;
            o[nf][2] *= al1; o[nf][3] *= al1;
        }

        uint32_t pah[4][4], pal[4][4];
        #pragma unroll
        for (int kk2 = 0; kk2 < 4; kk2++) {
            hl_pack(s[2 * kk2][0],     s[2 * kk2][1],     pah[kk2][0], pal[kk2][0]);
            hl_pack(s[2 * kk2][2],     s[2 * kk2][3],     pah[kk2][1], pal[kk2][1]);
            hl_pack(s[2 * kk2 + 1][0], s[2 * kk2 + 1][1], pah[kk2][2], pal[kk2][2]);
            hl_pack(s[2 * kk2 + 1][2], s[2 * kk2 + 1][3], pah[kk2][3], pal[kk2][3]);
        }

        #pragma unroll
        for (int kk2 = 0; kk2 < 4; kk2++) {
            #pragma unroll
            for (int jj = 0; jj < 8; jj++) {
                uint32_t vh4[4], vl4[4];
                ldm_x4_t(vh4, vH + kk2 * (16 * 272) + jj * 32);
                ldm_x4_t(vl4, vL + kk2 * (16 * 272) + jj * 32);
                mma16816(o[2 * jj],     pah[kk2], vh4);
                mma16816(o[2 * jj],     pah[kk2], vl4);
                mma16816(o[2 * jj],     pal[kk2], vh4);
                mma16816(o[2 * jj + 1], pah[kk2], vh4 + 2);
                mma16816(o[2 * jj + 1], pah[kk2], vl4 + 2);
                mma16816(o[2 * jj + 1], pal[kk2], vh4 + 2);
            }
        }
    }

    const float inv0 = 1.f / l0, inv1 = 1.f / l1;
    #pragma unroll
    for (int nf = 0; nf < 16; nf++) {
        int col = h * VD + nf * 8 + 2 * t;
        *(float2*)(ao + (size_t)row0g * DM + col) =
            make_float2(o[nf][0] * inv0, o[nf][1] * inv0);
        *(float2*)(ao + (size_t)(row0g + 8) * DM + col) =
            make_float2(o[nf][2] * inv1, o[nf][3] * inv1);
    }
}

// ---------------------------------------------------------------------------
extern "C" void kernel_launch(void* const* d_in, const int* in_sizes, int n_in,
                              void* d_out, int out_size)
{
    const float* x     = (const float*)d_in[0];
    const int*   mask  = (const int*)  d_in[1];
    const float* freqs = (const float*)d_in[2];
    const float* Wqa   = (const float*)d_in[3];
    const float* qln   = (const float*)d_in[4];
    const float* Wqb   = (const float*)d_in[5];
    const float* Wkva  = (const float*)d_in[6];
    const float* kvln  = (const float*)d_in[7];
    const float* Wkvb  = (const float*)d_in[8];
    const float* Wo    = (const float*)d_in[9];
    float* out = (float*)d_out;

    float *qlat, *ckv, *kv, *ao, *qbuf;
    cudaGetSymbolAddress((void**)&qlat, g_qlat);
    cudaGetSymbolAddress((void**)&ckv,  g_ckv);
    cudaGetSymbolAddress((void**)&kv,   g_kv);
    cudaGetSymbolAddress((void**)&ao,   g_ao);
    cudaGetSymbolAddress((void**)&qbuf, g_q);

    unsigned short *xh,*xl,*qlh,*qll,*ckh,*ckl,*aoh,*aol;
    unsigned short *WqaTh,*WqaTl,*WkvaTh,*WkvaTl,*WqbTh,*WqbTl,*WkvbTh,*WkvbTl,*WoTh,*WoTl;
    cudaGetSymbolAddress((void**)&xh,  g_xh);   cudaGetSymbolAddress((void**)&xl,  g_xl);
    cudaGetSymbolAddress((void**)&qlh, g_qlh);  cudaGetSymbolAddress((void**)&qll, g_qll);
    cudaGetSymbolAddress((void**)&ckh, g_ckh);  cudaGetSymbolAddress((void**)&ckl, g_ckl);
    cudaGetSymbolAddress((void**)&aoh, g_aoh);  cudaGetSymbolAddress((void**)&aol, g_aol);
    cudaGetSymbolAddress((void**)&WqaTh, g_WqaTh);   cudaGetSymbolAddress((void**)&WqaTl, g_WqaTl);
    cudaGetSymbolAddress((void**)&WkvaTh, g_WkvaTh); cudaGetSymbolAddress((void**)&WkvaTl, g_WkvaTl);
    cudaGetSymbolAddress((void**)&WqbTh, g_WqbTh);   cudaGetSymbolAddress((void**)&WqbTl, g_WqbTl);
    cudaGetSymbolAddress((void**)&WkvbTh, g_WkvbTh); cudaGetSymbolAddress((void**)&WkvbTl, g_WkvbTl);
    cudaGetSymbolAddress((void**)&WoTh, g_WoTh);     cudaGetSymbolAddress((void**)&WoTl, g_WoTl);

    cudaFuncSetAttribute(gemm_mma, cudaFuncAttributeMaxDynamicSharedMemorySize, GEMM_SMEM);
    cudaFuncSetAttribute(flash_mma, cudaFuncAttributeMaxDynamicSharedMemorySize, FL_SMEM_BYTES);
    dim3 blk(256);

    // my launch idx:                                                       // idx
    split2<<<(SEQ * DM + 255) / 256, blk>>>(x, xh, xl, SEQ * DM);           // 0
    transpose_split<<<dim3(QLORA / 32, DM / 32), blk>>>(Wqa, WqaTh, WqaTl, DM, QLORA); // 1
    transpose_split<<<dim3(KVWP / 32, DM / 32), blk>>>(Wkva, WkvaTh, WkvaTl, DM, KVW); // 2
    gemm_mma<<<dim3(QLORA / 128, SEQ / 128), blk, GEMM_SMEM>>>(             // 3 <- profiled
        xh, xl, DM, WqaTh, WqaTl, DM, qlat, QLORA, QLORA, DM);
    gemm_mma<<<dim3(KVWP / 128, SEQ / 128), blk, GEMM_SMEM>>>(
        xh, xl, DM, WkvaTh, WkvaTl, DM, ckv, KVW, KVW, DM);
    rmsnorm_kernel<<<SEQ, 256>>>(qlat, qln, QLORA, QLORA);
    rmsnorm_kernel<<<SEQ, 256>>>(ckv, kvln, KVLORA, KVW);
    split2<<<(SEQ * QLORA + 255) / 256, blk>>>(qlat, qlh, qll, SEQ * QLORA);
    split2<<<(SEQ * KVW + 255) / 256, blk>>>(ckv, ckh, ckl, SEQ * KVW);
    transpose_split<<<dim3(NQ / 32, QLORA / 32), blk>>>(Wqb, WqbTh, WqbTl, QLORA, NQ);
    transpose_split<<<dim3(NKV / 32, KVLORA / 32), blk>>>(Wkvb, WkvbTh, WkvbTl, KVLORA, NKV);
    gemm_mma<<<dim3(NQ / 128, SEQ / 128), blk, GEMM_SMEM>>>(
        qlh, qll, QLORA, WqbTh, WqbTl, QLORA, qbuf, NQ, NQ, QLORA);
    gemm_mma<<<dim3(NKV / 128, SEQ / 128), blk, GEMM_SMEM>>>(
        ckh, ckl, KVW, WkvbTh, WkvbTl, KVLORA, kv, NKV, NKV, KVLORA);

    build_qk<<<SEQ, 256>>>(freqs);
    flash_mma<<<dim3(SEQ / 128, NHEAD), blk, FL_SMEM_BYTES>>>(mask, ao);

    transpose_split<<<dim3(DM / 32, DM / 32), blk>>>(Wo, WoTh, WoTl, DM, DM);
    split2<<<(SEQ * DM + 255) / 256, blk>>>(ao, aoh, aol, SEQ * DM);
    gemm_mma<<<dim3(DM / 128, SEQ / 128), blk, GEMM_SMEM>>>(
        aoh, aol, DM, WoTh, WoTl, DM, out, DM, DM, DM);
}

// round 14
// speedup vs baseline: 1.0512x; 1.0512x over previous
// R12: gemm_mma v3 — 512 threads (16 warps, 4x4 warp grid, 32x32 warp tile),
// K-chunk 32, 3-stage cp.async ring (120KB), persistent tile-stride grid.
// R11 post-mortem: tensor=30%, occ=16% -> latency-bound, wave-quantized.
// Flash unchanged. Best: R10 = 1559.2us.
#include <cuda_runtime.h>
#include <cuda_bf16.h>
#include <math.h>
#include <stdint.h>

#define SEQ    2048
#define DM     2048
#define NHEAD  16
#define QLORA  1536
#define KVLORA 512
#define ROPED  64
#define NOPED  128
#define VD     128
#define QHDIM  192
#define KVW    576
#define KVROW  256
#define MASKW  2198
#define NEG_BIG (-1e30f)

#define NQ   (NHEAD * QHDIM)   // 3072
#define NKV  (NHEAD * KVROW)   // 4096
#define KVWP 640

// ---------------- fp32 scratch ----------------
__device__ float g_qlat[SEQ * QLORA];
__device__ float g_ckv [SEQ * KVW];
__device__ float g_q   [SEQ * NQ];
__device__ float g_kv  [SEQ * NKV];
__device__ float g_ao  [SEQ * DM];

// ---------------- bf16 hi/lo split buffers ----------------
__device__ unsigned short g_xh [SEQ * DM],    g_xl [SEQ * DM];
__device__ unsigned short g_qlh[SEQ * QLORA], g_qll[SEQ * QLORA];
__device__ unsigned short g_ckh[SEQ * KVW],   g_ckl[SEQ * KVW];
__device__ unsigned short g_aoh[SEQ * DM],    g_aol[SEQ * DM];
__device__ unsigned short g_WqaTh [QLORA * DM],  g_WqaTl [QLORA * DM];
__device__ unsigned short g_WkvaTh[KVWP  * DM],  g_WkvaTl[KVWP  * DM];
__device__ unsigned short g_WqbTh [NQ * QLORA],  g_WqbTl [NQ * QLORA];
__device__ unsigned short g_WkvbTh[NKV * KVLORA],g_WkvbTl[NKV * KVLORA];
__device__ unsigned short g_WoTh  [DM * DM],     g_WoTl  [DM * DM];
__device__ unsigned short g_Qbh[NHEAD * SEQ * QHDIM], g_Qbl[NHEAD * SEQ * QHDIM];
__device__ unsigned short g_Kbh[NHEAD * SEQ * QHDIM], g_Kbl[NHEAD * SEQ * QHDIM];
__device__ unsigned short g_Vbh[NHEAD * SEQ * VD],    g_Vbl[NHEAD * SEQ * VD];

// ======================= PTX helpers =======================
__device__ __forceinline__ uint32_t smem_u32(const void* p) {
    uint32_t a;
    asm("{ .reg .u64 t; cvta.to.shared.u64 t, %1; cvt.u32.u64 %0, t; }"
        : "=r"(a) : "l"(p));
    return a;
}
__device__ __forceinline__ void ldm_x4(uint32_t* r, uint32_t a) {
    asm volatile("ldmatrix.sync.aligned.m8n8.x4.shared.b16 {%0,%1,%2,%3}, [%4];"
        : "=r"(r[0]), "=r"(r[1]), "=r"(r[2]), "=r"(r[3]) : "r"(a));
}
__device__ __forceinline__ void ldm_x4_t(uint32_t* r, uint32_t a) {
    asm volatile("ldmatrix.sync.aligned.m8n8.x4.trans.shared.b16 {%0,%1,%2,%3}, [%4];"
        : "=r"(r[0]), "=r"(r[1]), "=r"(r[2]), "=r"(r[3]) : "r"(a));
}
__device__ __forceinline__ void mma16816(float* c, const uint32_t* a, const uint32_t* b) {
    asm volatile(
        "mma.sync.aligned.m16n8k16.row.col.f32.bf16.bf16.f32 "
        "{%0,%1,%2,%3}, {%4,%5,%6,%7}, {%8,%9}, {%0,%1,%2,%3};"
        : "+f"(c[0]), "+f"(c[1]), "+f"(c[2]), "+f"(c[3])
        : "r"(a[0]), "r"(a[1]), "r"(a[2]), "r"(a[3]), "r"(b[0]), "r"(b[1]));
}
__device__ __forceinline__ void cp16(uint32_t dst, const void* src) {
    asm volatile("cp.async.cg.shared.global [%0], [%1], 16;" :: "r"(dst), "l"(src));
}
#define CP_COMMIT() asm volatile("cp.async.commit_group;" ::: "memory")
#define CP_WAIT2()  asm volatile("cp.async.wait_group 2;" ::: "memory")

__device__ __forceinline__ void bsplit(float v, unsigned short& h, unsigned short& l) {
    __nv_bfloat16 bh = __float2bfloat16(v);
    __nv_bfloat16 bl = __float2bfloat16(v - __bfloat162float(bh));
    h = __bfloat16_as_ushort(bh);
    l = __bfloat16_as_ushort(bl);
}
__device__ __forceinline__ void hl_pack(float x, float y, uint32_t& hr, uint32_t& lr) {
    __nv_bfloat16 xh = __float2bfloat16(x);
    __nv_bfloat16 yh = __float2bfloat16(y);
    __nv_bfloat16 xl = __float2bfloat16(x - __bfloat162float(xh));
    __nv_bfloat16 yl = __float2bfloat16(y - __bfloat162float(yh));
    hr = (uint32_t)__bfloat16_as_ushort(xh) | ((uint32_t)__bfloat16_as_ushort(yh) << 16);
    lr = (uint32_t)__bfloat16_as_ushort(xl) | ((uint32_t)__bfloat16_as_ushort(yl) << 16);
}

// ======================= prep kernels =======================
__global__ void __launch_bounds__(256) split2(
    const float* __restrict__ src, unsigned short* __restrict__ h,
    unsigned short* __restrict__ l, int n)
{
    int i = blockIdx.x * 256 + threadIdx.x;
    if (i < n) bsplit(src[i], h[i], l[i]);
}

__global__ void __launch_bounds__(256) transpose_split(
    const float* __restrict__ W, unsigned short* __restrict__ Th,
    unsigned short* __restrict__ Tl, int K, int N)
{
    __shared__ float t[32][33];
    int n0 = blockIdx.x * 32, k0 = blockIdx.y * 32;
    int tx = threadIdx.x & 31, ty = threadIdx.x >> 5;
    #pragma unroll
    for (int i = 0; i < 4; i++) {
        int k = k0 + ty + i * 8, n = n0 + tx;
        t[ty + i * 8][tx] = (n < N) ? W[(size_t)k * N + n] : 0.f;
    }
    __syncthreads();
    #pragma unroll
    for (int i = 0; i < 4; i++) {
        int n = n0 + ty + i * 8, k = k0 + tx;
        bsplit(t[tx][ty + i * 8], Th[(size_t)n * K + k], Tl[(size_t)n * K + k]);
    }
}

// ========= HMMA split GEMM v3: 512 thr, 4x4 warps, 3-stage, persistent =====
// smem row: 32 bf16 (64B) + 16B pad = 80B stride. Tensor tile 128x80B = 10240B.
#define T_STRIDE_US 40
#define TEN_US      (128 * 40)      // 5120 us
#define STAGE_US    (4 * TEN_US)    // 20480 us = 40960 B
#define GEMM_SMEM   (3 * STAGE_US * 2)   // 122880 B

__global__ void __launch_bounds__(512) gemm_mma(
    const unsigned short* __restrict__ Ahp, const unsigned short* __restrict__ Alp, int lda,
    const unsigned short* __restrict__ Bhp, const unsigned short* __restrict__ Blp, int ldb,
    float* __restrict__ C, int ldc, int N, int K, int ntx, int ntiles)
{
    extern __shared__ unsigned short smus[];
    const uint32_t sbase = smem_u32(smus);
    const int tid  = threadIdx.x;
    const int lane = tid & 31;
    const int wid  = tid >> 5;
    const int wm   = wid & 3;        // 0..3 m
    const int wn   = wid >> 2;       // 0..3 n
    const int NC   = K >> 5;

    // ldmatrix per-thread offsets (80B row stride)
    const uint32_t aoff = (uint32_t)((wm * 32 + (lane & 15)) * 80 + (lane >> 4) * 16);
    const uint32_t boff = (uint32_t)((wn * 32 + ((lane >> 4) * 8) + (lane & 7)) * 80
                                     + (((lane >> 3) & 1) * 16));
    // copy mapping: 4 x 16B per thread; tensor index = i (compile-time)
    const int cp_r = (tid & 511) >> 2;
    const int cp_c = tid & 3;

    for (int tile = blockIdx.x; tile < ntiles; tile += gridDim.x) {
        const int row0 = (tile / ntx) * 128;
        const int col0 = (tile % ntx) * 128;
        const unsigned short* bases[4] = { Ahp, Alp, Bhp, Blp };
        const int ldv[4] = { lda, lda, ldb, ldb };
        const int rbv[4] = { row0, row0, col0, col0 };

        float acc[2][4][4];
        #pragma unroll
        for (int i = 0; i < 2; i++)
            #pragma unroll
            for (int j = 0; j < 4; j++)
                #pragma unroll
                for (int q = 0; q < 4; q++) acc[i][j][q] = 0.f;

        auto issue_chunk = [&](int c, int s) {
            const int k0 = c << 5;
            const uint32_t sb = sbase + (uint32_t)s * (STAGE_US * 2);
            // thread covers one (row, 16B) slot in each of the 4 tensors:
            // 512 threads x 4 tensors = 4 x (128 rows x 4 chunks)
            #pragma unroll
            for (int t = 0; t < 4; t++) {
                cp16(sb + (uint32_t)(t * TEN_US + cp_r * T_STRIDE_US + cp_c * 8) * 2,
                     bases[t] + (size_t)(rbv[t] + cp_r) * ldv[t] + k0 + cp_c * 8);
            }
            CP_COMMIT();
        };

        issue_chunk(0, 0);
        issue_chunk(1, 1);

        for (int c = 0; c < NC; c++) {
            const int s = c - (c / 3) * 3;       // c % 3
            if (c + 2 < NC) issue_chunk(c + 2, (c + 2) - ((c + 2) / 3) * 3);
            else            CP_COMMIT();
            CP_WAIT2();
            __syncthreads();

            const uint32_t st = sbase + (uint32_t)s * (STAGE_US * 2);
            #pragma unroll
            for (int ks = 0; ks < 2; ks++) {
                const uint32_t kb = (uint32_t)(ks * 32);
                uint32_t Ah[2][4], Al[2][4], Bh[4][2], Bl[4][2];
                #pragma unroll
                for (int mf = 0; mf < 2; mf++) {
                    ldm_x4(Ah[mf], st + 0          + aoff + (uint32_t)(mf * 16 * 80) + kb);
                    ldm_x4(Al[mf], st + TEN_US * 2 + aoff + (uint32_t)(mf * 16 * 80) + kb);
                }
                #pragma unroll
                for (int np = 0; np < 2; np++) {
                    uint32_t rh[4], rl[4];
                    ldm_x4(rh, st + TEN_US * 4 + boff + (uint32_t)(np * 16 * 80) + kb);
                    ldm_x4(rl, st + TEN_US * 6 + boff + (uint32_t)(np * 16 * 80) + kb);
                    Bh[np * 2][0] = rh[0]; Bh[np * 2][1] = rh[1];
                    Bh[np * 2 + 1][0] = rh[2]; Bh[np * 2 + 1][1] = rh[3];
                    Bl[np * 2][0] = rl[0]; Bl[np * 2][1] = rl[1];
                    Bl[np * 2 + 1][0] = rl[2]; Bl[np * 2 + 1][1] = rl[3];
                }
                #pragma unroll
                for (int mf = 0; mf < 2; mf++)
                    #pragma unroll
                    for (int nf = 0; nf < 4; nf++) {
                        mma16816(acc[mf][nf], Ah[mf], Bh[nf]);
                        mma16816(acc[mf][nf], Ah[mf], Bl[nf]);
                        mma16816(acc[mf][nf], Al[mf], Bh[nf]);
                    }
            }
            __syncthreads();
        }

        #pragma unroll
        for (int mf = 0; mf < 2; mf++) {
            int r0 = row0 + wm * 32 + mf * 16 + (lane >> 2);
            #pragma unroll
            for (int nf = 0; nf < 4; nf++) {
                int c0 = col0 + wn * 32 + nf * 8 + (lane & 3) * 2;
                if (c0 < N) {
                    C[(size_t)r0 * ldc + c0] = acc[mf][nf][0];
                    C[(size_t)(r0 + 8) * ldc + c0] = acc[mf][nf][2];
                }
                if (c0 + 1 < N) {
                    C[(size_t)r0 * ldc + c0 + 1] = acc[mf][nf][1];
                    C[(size_t)(r0 + 8) * ldc + c0 + 1] = acc[mf][nf][3];
                }
            }
        }
        __syncthreads();
    }
}

// ======================= rmsnorm =======================
__global__ void __launch_bounds__(256) rmsnorm_kernel(
    float* __restrict__ data, const float* __restrict__ w, int W, int ld)
{
    const int row = blockIdx.x;
    float* p = data + (size_t)row * ld;
    float ss = 0.f;
    for (int c = threadIdx.x; c < W; c += 256) { float v = p[c]; ss += v * v; }
    __shared__ float red[256];
    red[threadIdx.x] = ss;
    __syncthreads();
    #pragma unroll
    for (int s = 128; s > 0; s >>= 1) {
        if (threadIdx.x < s) red[threadIdx.x] += red[threadIdx.x + s];
        __syncthreads();
    }
    float scale = rsqrtf(red[0] / (float)W + 1e-6f);
    for (int c = threadIdx.x; c < W; c += 256) p[c] = w[c] * (p[c] * scale);
}

// ======================= rope + per-head bf16 hi/lo layout =================
__global__ void __launch_bounds__(256) build_qk(const float* __restrict__ freqs)
{
    const int s = blockIdx.x;
    const int tid = threadIdx.x;
    __shared__ float cs[32], sn[32];
    if (tid < 32) {
        cs[tid] = freqs[(s * 32 + tid) * 2 + 0];
        sn[tid] = freqs[(s * 32 + tid) * 2 + 1];
    }
    __syncthreads();

    const float* qrow = g_q + (size_t)s * NQ;
    for (int idx = tid; idx < NQ; idx += 256) {
        int hh = idx / QHDIM, d = idx % QHDIM;
        float val;
        if (d < ROPED) {
            int j = d >> 1;
            float a = qrow[hh * QHDIM + NOPED + 2 * j];
            float b = qrow[hh * QHDIM + NOPED + 2 * j + 1];
            val = (d & 1) ? (a * sn[j] + b * cs[j]) : (a * cs[j] - b * sn[j]);
        } else {
            val = qrow[hh * QHDIM + (d - ROPED)];
        }
        size_t off = ((size_t)hh * SEQ + s) * QHDIM + d;
        bsplit(val, g_Qbh[off], g_Qbl[off]);
    }

    const float* kperow = g_ckv + (size_t)s * KVW + KVLORA;
    const float* kvrow  = g_kv  + (size_t)s * NKV;
    for (int idx = tid; idx < NQ; idx += 256) {
        int hh = idx / QHDIM, d = idx % QHDIM;
        float val;
        if (d < ROPED) {
            int j = d >> 1;
            float a = kperow[2 * j], b = kperow[2 * j + 1];
            val = (d & 1) ? (a * sn[j] + b * cs[j]) : (a * cs[j] - b * sn[j]);
        } else {
            val = kvrow[hh * KVROW + (d - ROPED)];
        }
        size_t off = ((size_t)hh * SEQ + s) * QHDIM + d;
        bsplit(val, g_Kbh[off], g_Kbl[off]);
    }

    for (int idx = tid; idx < NHEAD * VD; idx += 256) {
        int hh = idx / VD, d = idx % VD;
        float v = kvrow[hh * KVROW + NOPED + d];
        size_t off = ((size_t)hh * SEQ + s) * VD + d;
        bsplit(v, g_Vbh[off], g_Vbl[off]);
    }
}

// ======================= HMMA flash attention (unchanged R9) ==============
#define FL_SMEM_BYTES 188416

__global__ void __launch_bounds__(256) flash_mma(
    const int* __restrict__ mask, float* __restrict__ ao)
{
    extern __shared__ unsigned short fsm[];
    const uint32_t sb = smem_u32(fsm);
    const int tid  = threadIdx.x;
    const int lane = tid & 31;
    const int wq   = tid >> 5;
    const int qb   = blockIdx.x;
    const int h    = blockIdx.y;
    const int g    = lane >> 2;
    const int t    = lane & 3;
    const int bq   = lane >> 3;
    const int br   = lane & 7;
    const float scale = 0.088388347648318447f;

    unsigned short* Qh_s = fsm;
    unsigned short* Ql_s = fsm + 25600;
    unsigned short* Kh_s = fsm + 51200;
    unsigned short* Kl_s = fsm + 64000;
    unsigned short* Vh_s = fsm + 76800;
    unsigned short* Vl_s = fsm + 85504;

    const uint32_t aH = sb + (uint32_t)((wq * 16 + (lane & 15)) * 400 + (lane >> 4) * 16);
    const uint32_t aL = aH + 51200;
    const uint32_t kH = sb + 102400 + (uint32_t)(((bq >> 1) * 8 + br) * 400 + (bq & 1) * 16);
    const uint32_t kL = kH + 25600;
    const uint32_t vH = sb + 153600 + (uint32_t)(((bq & 1) * 8 + br) * 272 + (bq >> 1) * 16);
    const uint32_t vL = vH + 17408;

    const size_t qgo = ((size_t)h * SEQ + (size_t)qb * 128) * QHDIM;
    for (int i = tid; i < 128 * 24; i += 256) {
        int r = i / 24, c = i % 24;
        *(uint4*)(Qh_s + r * 200 + c * 8) = *(const uint4*)(g_Qbh + qgo + (size_t)r * QHDIM + c * 8);
        *(uint4*)(Ql_s + r * 200 + c * 8) = *(const uint4*)(g_Qbl + qgo + (size_t)r * QHDIM + c * 8);
    }

    float o[16][4];
    #pragma unroll
    for (int i = 0; i < 16; i++)
        #pragma unroll
        for (int j = 0; j < 4; j++) o[i][j] = 0.f;
    float mr0 = NEG_BIG, mr1 = NEG_BIG, l0 = 0.f, l1 = 0.f;

    const int row0g = qb * 128 + wq * 16 + g;

    for (int kb = 0; kb < SEQ / 64; kb++) {
        __syncthreads();
        const size_t kgo = ((size_t)h * SEQ + (size_t)kb * 64) * QHDIM;
        for (int i = tid; i < 64 * 24; i += 256) {
            int r = i / 24, c = i % 24;
            *(uint4*)(Kh_s + r * 200 + c * 8) = *(const uint4*)(g_Kbh + kgo + (size_t)r * QHDIM + c * 8);
            *(uint4*)(Kl_s + r * 200 + c * 8) = *(const uint4*)(g_Kbl + kgo + (size_t)r * QHDIM + c * 8);
        }
        const size_t vgo = ((size_t)h * SEQ + (size_t)kb * 64) * VD;
        for (int i = tid; i < 64 * 16; i += 256) {
            int r = i / 16, c = i % 16;
            *(uint4*)(Vh_s + r * 136 + c * 8) = *(const uint4*)(g_Vbh + vgo + (size_t)r * VD + c * 8);
            *(uint4*)(Vl_s + r * 136 + c * 8) = *(const uint4*)(g_Vbl + vgo + (size_t)r * VD + c * 8);
        }
        __syncthreads();

        float s[8][4];
        #pragma unroll
        for (int f = 0; f < 8; f++)
            #pragma unroll
            for (int e = 0; e < 4; e++) s[f][e] = 0.f;

        #pragma unroll
        for (int kk = 0; kk < 12; kk++) {
            uint32_t ah[4], al[4];
            ldm_x4(ah, aH + kk * 32);
            ldm_x4(al, aL + kk * 32);
            #pragma unroll
            for (int np = 0; np < 4; np++) {
                uint32_t bh[4], bl[4];
                ldm_x4(bh, kH + np * (16 * 400) + kk * 32);
                ldm_x4(bl, kL + np * (16 * 400) + kk * 32);
                mma16816(s[2 * np],     ah, bh);
                mma16816(s[2 * np],     ah, bl);
                mma16816(s[2 * np],     al, bh);
                mma16816(s[2 * np + 1], ah, bh + 2);
                mma16816(s[2 * np + 1], ah, bl + 2);
                mma16816(s[2 * np + 1], al, bh + 2);
            }
        }

        #pragma unroll
        for (int f = 0; f < 8; f++)
            #pragma unroll
            for (int e = 0; e < 4; e++) s[f][e] *= scale;

        const int colbase = 150 + kb * 64;
        #pragma unroll
        for (int f = 0; f < 8; f++) {
            int col = colbase + f * 8 + 2 * t;
            int2 m0v = *(const int2*)(mask + (size_t)row0g * MASKW + col);
            int2 m1v = *(const int2*)(mask + (size_t)(row0g + 8) * MASKW + col);
            if (m0v.x == 1) s[f][0] = NEG_BIG;
            if (m0v.y == 1) s[f][1] = NEG_BIG;
            if (m1v.x == 1) s[f][2] = NEG_BIG;
            if (m1v.y == 1) s[f][3] = NEG_BIG;
        }

        float m0 = NEG_BIG, m1 = NEG_BIG;
        #pragma unroll
        for (int f = 0; f < 8; f++) {
            m0 = fmaxf(m0, fmaxf(s[f][0], s[f][1]));
            m1 = fmaxf(m1, fmaxf(s[f][2], s[f][3]));
        }
        m0 = fmaxf(m0, __shfl_xor_sync(0xffffffffu, m0, 1));
        m0 = fmaxf(m0, __shfl_xor_sync(0xffffffffu, m0, 2));
        m1 = fmaxf(m1, __shfl_xor_sync(0xffffffffu, m1, 1));
        m1 = fmaxf(m1, __shfl_xor_sync(0xffffffffu, m1, 2));
        float nm0 = fmaxf(mr0, m0), nm1 = fmaxf(mr1, m1);
        float al0 = __expf(mr0 - nm0), al1 = __expf(mr1 - nm1);
        mr0 = nm0; mr1 = nm1;

        float sum0 = 0.f, sum1 = 0.f;
        #pragma unroll
        for (int f = 0; f < 8; f++) {
            s[f][0] = __expf(s[f][0] - nm0);
            s[f][1] = __expf(s[f][1] - nm0);
            s[f][2] = __expf(s[f][2] - nm1);
            s[f][3] = __expf(s[f][3] - nm1);
            sum0 += s[f][0] + s[f][1];
            sum1 += s[f][2] + s[f][3];
        }
        sum0 += __shfl_xor_sync(0xffffffffu, sum0, 1);
        sum0 += __shfl_xor_sync(0xffffffffu, sum0, 2);
        sum1 += __shfl_xor_sync(0xffffffffu, sum1, 1);
        sum1 += __shfl_xor_sync(0xffffffffu, sum1, 2);
        l0 = l0 * al0 + sum0;
        l1 = l1 * al1 + sum1;

        #pragma unroll
        for (int nf = 0; nf < 16; nf++) {
            o[nf][0] *= al0; o[nf][1] *= al0;
            o[nf][2] *= al1; o[nf][3] *= al1;
        }

        uint32_t pah[4][4], pal[4][4];
        #pragma unroll
        for (int kk2 = 0; kk2 < 4; kk2++) {
            hl_pack(s[2 * kk2][0],     s[2 * kk2][1],     pah[kk2][0], pal[kk2][0]);
            hl_pack(s[2 * kk2][2],     s[2 * kk2][3],     pah[kk2][1], pal[kk2][1]);
            hl_pack(s[2 * kk2 + 1][0], s[2 * kk2 + 1][1], pah[kk2][2], pal[kk2][2]);
            hl_pack(s[2 * kk2 + 1][2], s[2 * kk2 + 1][3], pah[kk2][3], pal[kk2][3]);
        }

        #pragma unroll
        for (int kk2 = 0; kk2 < 4; kk2++) {
            #pragma unroll
            for (int jj = 0; jj < 8; jj++) {
                uint32_t vh4[4], vl4[4];
                ldm_x4_t(vh4, vH + kk2 * (16 * 272) + jj * 32);
                ldm_x4_t(vl4, vL + kk2 * (16 * 272) + jj * 32);
                mma16816(o[2 * jj],     pah[kk2], vh4);
                mma16816(o[2 * jj],     pah[kk2], vl4);
                mma16816(o[2 * jj],     pal[kk2], vh4);
                mma16816(o[2 * jj + 1], pah[kk2], vh4 + 2);
                mma16816(o[2 * jj + 1], pah[kk2], vl4 + 2);
                mma16816(o[2 * jj + 1], pal[kk2], vh4 + 2);
            }
        }
    }

    const float inv0 = 1.f / l0, inv1 = 1.f / l1;
    #pragma unroll
    for (int nf = 0; nf < 16; nf++) {
        int col = h * VD + nf * 8 + 2 * t;
        *(float2*)(ao + (size_t)row0g * DM + col) =
            make_float2(o[nf][0] * inv0, o[nf][1] * inv0);
        *(float2*)(ao + (size_t)(row0g + 8) * DM + col) =
            make_float2(o[nf][2] * inv1, o[nf][3] * inv1);
    }
}

// ---------------------------------------------------------------------------
static inline int mini(int a, int b) { return a < b ? a : b; }

extern "C" void kernel_launch(void* const* d_in, const int* in_sizes, int n_in,
                              void* d_out, int out_size)
{
    const float* x     = (const float*)d_in[0];
    const int*   mask  = (const int*)  d_in[1];
    const float* freqs = (const float*)d_in[2];
    const float* Wqa   = (const float*)d_in[3];
    const float* qln   = (const float*)d_in[4];
    const float* Wqb   = (const float*)d_in[5];
    const float* Wkva  = (const float*)d_in[6];
    const float* kvln  = (const float*)d_in[7];
    const float* Wkvb  = (const float*)d_in[8];
    const float* Wo    = (const float*)d_in[9];
    float* out = (float*)d_out;

    float *qlat, *ckv, *kv, *ao, *qbuf;
    cudaGetSymbolAddress((void**)&qlat, g_qlat);
    cudaGetSymbolAddress((void**)&ckv,  g_ckv);
    cudaGetSymbolAddress((void**)&kv,   g_kv);
    cudaGetSymbolAddress((void**)&ao,   g_ao);
    cudaGetSymbolAddress((void**)&qbuf, g_q);

    unsigned short *xh,*xl,*qlh,*qll,*ckh,*ckl,*aoh,*aol;
    unsigned short *WqaTh,*WqaTl,*WkvaTh,*WkvaTl,*WqbTh,*WqbTl,*WkvbTh,*WkvbTl,*WoTh,*WoTl;
    cudaGetSymbolAddress((void**)&xh,  g_xh);   cudaGetSymbolAddress((void**)&xl,  g_xl);
    cudaGetSymbolAddress((void**)&qlh, g_qlh);  cudaGetSymbolAddress((void**)&qll, g_qll);
    cudaGetSymbolAddress((void**)&ckh, g_ckh);  cudaGetSymbolAddress((void**)&ckl, g_ckl);
    cudaGetSymbolAddress((void**)&aoh, g_aoh);  cudaGetSymbolAddress((void**)&aol, g_aol);
    cudaGetSymbolAddress((void**)&WqaTh, g_WqaTh);   cudaGetSymbolAddress((void**)&WqaTl, g_WqaTl);
    cudaGetSymbolAddress((void**)&WkvaTh, g_WkvaTh); cudaGetSymbolAddress((void**)&WkvaTl, g_WkvaTl);
    cudaGetSymbolAddress((void**)&WqbTh, g_WqbTh);   cudaGetSymbolAddress((void**)&WqbTl, g_WqbTl);
    cudaGetSymbolAddress((void**)&WkvbTh, g_WkvbTh); cudaGetSymbolAddress((void**)&WkvbTl, g_WkvbTl);
    cudaGetSymbolAddress((void**)&WoTh, g_WoTh);     cudaGetSymbolAddress((void**)&WoTl, g_WoTl);

    cudaFuncSetAttribute(gemm_mma, cudaFuncAttributeMaxDynamicSharedMemorySize, GEMM_SMEM);
    cudaFuncSetAttribute(flash_mma, cudaFuncAttributeMaxDynamicSharedMemorySize, FL_SMEM_BYTES);
    dim3 blk(256);
    dim3 gblk(512);

    // tile counts (over padded N for B indexing)
    const int t1 = (QLORA / 128) * (SEQ / 128);   // 192
    const int t2 = (KVWP  / 128) * (SEQ / 128);   // 80
    const int t3 = (NQ    / 128) * (SEQ / 128);   // 384
    const int t4 = (NKV   / 128) * (SEQ / 128);   // 512
    const int t5 = (DM    / 128) * (SEQ / 128);   // 256

    // my launch idx:                                                       // idx
    split2<<<(SEQ * DM + 255) / 256, blk>>>(x, xh, xl, SEQ * DM);           // 0
    transpose_split<<<dim3(QLORA / 32, DM / 32), blk>>>(Wqa, WqaTh, WqaTl, DM, QLORA); // 1
    transpose_split<<<dim3(KVWP / 32, DM / 32), blk>>>(Wkva, WkvaTh, WkvaTl, DM, KVW); // 2
    gemm_mma<<<mini(t1, 148), gblk, GEMM_SMEM>>>(                           // 3 <- profiled
        xh, xl, DM, WqaTh, WqaTl, DM, qlat, QLORA, QLORA, DM, QLORA / 128, t1);
    gemm_mma<<<mini(t2, 148), gblk, GEMM_SMEM>>>(
        xh, xl, DM, WkvaTh, WkvaTl, DM, ckv, KVW, KVW, DM, KVWP / 128, t2);
    rmsnorm_kernel<<<SEQ, 256>>>(qlat, qln, QLORA, QLORA);
    rmsnorm_kernel<<<SEQ, 256>>>(ckv, kvln, KVLORA, KVW);
    split2<<<(SEQ * QLORA + 255) / 256, blk>>>(qlat, qlh, qll, SEQ * QLORA);
    split2<<<(SEQ * KVW + 255) / 256, blk>>>(ckv, ckh, ckl, SEQ * KVW);
    transpose_split<<<dim3(NQ / 32, QLORA / 32), blk>>>(Wqb, WqbTh, WqbTl, QLORA, NQ);
    transpose_split<<<dim3(NKV / 32, KVLORA / 32), blk>>>(Wkvb, WkvbTh, WkvbTl, KVLORA, NKV);
    gemm_mma<<<mini(t3, 148), gblk, GEMM_SMEM>>>(
        qlh, qll, QLORA, WqbTh, WqbTl, QLORA, qbuf, NQ, NQ, QLORA, NQ / 128, t3);
    gemm_mma<<<mini(t4, 148), gblk, GEMM_SMEM>>>(
        ckh, ckl, KVW, WkvbTh, WkvbTl, KVLORA, kv, NKV, NKV, KVLORA, NKV / 128, t4);

    build_qk<<<SEQ, 256>>>(freqs);
    flash_mma<<<dim3(SEQ / 128, NHEAD), blk, FL_SMEM_BYTES>>>(mask, ao);

    transpose_split<<<dim3(DM / 32, DM / 32), blk>>>(Wo, WoTh, WoTl, DM, DM);
    split2<<<(SEQ * DM + 255) / 256, blk>>>(ao, aoh, aol, SEQ * DM);
    gemm_mma<<<mini(t5, 148), gblk, GEMM_SMEM>>>(
        aoh, aol, DM, WoTh, WoTl, DM, out, DM, DM, DM, DM / 128, t5);
}

// round 16
// speedup vs baseline: 1.2180x; 1.1587x over previous
// R15: gemm_mma v5 — 3-stage cp.async ring with ONE race-free barrier/chunk
// (wait BEFORE sync; overwrite distance 2), XOR-swizzled 64B rows (96KB ->
// 2 CTAs/SM), persistent grid. R14's race (sync before wait) fixed.
// Flash unchanged. Best: R12 = 1556.7us.
#include <cuda_runtime.h>
#include <cuda_bf16.h>
#include <math.h>
#include <stdint.h>

#define SEQ    2048
#define DM     2048
#define NHEAD  16
#define QLORA  1536
#define KVLORA 512
#define ROPED  64
#define NOPED  128
#define VD     128
#define QHDIM  192
#define KVW    576
#define KVROW  256
#define MASKW  2198
#define NEG_BIG (-1e30f)

#define NQ   (NHEAD * QHDIM)   // 3072
#define NKV  (NHEAD * KVROW)   // 4096
#define KVWP 640

// ---------------- fp32 scratch ----------------
__device__ float g_qlat[SEQ * QLORA];
__device__ float g_ckv [SEQ * KVW];
__device__ float g_q   [SEQ * NQ];
__device__ float g_kv  [SEQ * NKV];
__device__ float g_ao  [SEQ * DM];

// ---------------- bf16 hi/lo split buffers ----------------
__device__ unsigned short g_xh [SEQ * DM],    g_xl [SEQ * DM];
__device__ unsigned short g_qlh[SEQ * QLORA], g_qll[SEQ * QLORA];
__device__ unsigned short g_ckh[SEQ * KVW],   g_ckl[SEQ * KVW];
__device__ unsigned short g_aoh[SEQ * DM],    g_aol[SEQ * DM];
__device__ unsigned short g_WqaTh [QLORA * DM],  g_WqaTl [QLORA * DM];
__device__ unsigned short g_WkvaTh[KVWP  * DM],  g_WkvaTl[KVWP  * DM];
__device__ unsigned short g_WqbTh [NQ * QLORA],  g_WqbTl [NQ * QLORA];
__device__ unsigned short g_WkvbTh[NKV * KVLORA],g_WkvbTl[NKV * KVLORA];
__device__ unsigned short g_WoTh  [DM * DM],     g_WoTl  [DM * DM];
__device__ unsigned short g_Qbh[NHEAD * SEQ * QHDIM], g_Qbl[NHEAD * SEQ * QHDIM];
__device__ unsigned short g_Kbh[NHEAD * SEQ * QHDIM], g_Kbl[NHEAD * SEQ * QHDIM];
__device__ unsigned short g_Vbh[NHEAD * SEQ * VD],    g_Vbl[NHEAD * SEQ * VD];

// ======================= PTX helpers =======================
__device__ __forceinline__ uint32_t smem_u32(const void* p) {
    uint32_t a;
    asm("{ .reg .u64 t; cvta.to.shared.u64 t, %1; cvt.u32.u64 %0, t; }"
        : "=r"(a) : "l"(p));
    return a;
}
__device__ __forceinline__ void ldm_x4(uint32_t* r, uint32_t a) {
    asm volatile("ldmatrix.sync.aligned.m8n8.x4.shared.b16 {%0,%1,%2,%3}, [%4];"
        : "=r"(r[0]), "=r"(r[1]), "=r"(r[2]), "=r"(r[3]) : "r"(a));
}
__device__ __forceinline__ void ldm_x4_t(uint32_t* r, uint32_t a) {
    asm volatile("ldmatrix.sync.aligned.m8n8.x4.trans.shared.b16 {%0,%1,%2,%3}, [%4];"
        : "=r"(r[0]), "=r"(r[1]), "=r"(r[2]), "=r"(r[3]) : "r"(a));
}
__device__ __forceinline__ void mma16816(float* c, const uint32_t* a, const uint32_t* b) {
    asm volatile(
        "mma.sync.aligned.m16n8k16.row.col.f32.bf16.bf16.f32 "
        "{%0,%1,%2,%3}, {%4,%5,%6,%7}, {%8,%9}, {%0,%1,%2,%3};"
        : "+f"(c[0]), "+f"(c[1]), "+f"(c[2]), "+f"(c[3])
        : "r"(a[0]), "r"(a[1]), "r"(a[2]), "r"(a[3]), "r"(b[0]), "r"(b[1]));
}
__device__ __forceinline__ void cp16(uint32_t dst, const void* src) {
    asm volatile("cp.async.cg.shared.global [%0], [%1], 16;" :: "r"(dst), "l"(src));
}
#define CP_COMMIT() asm volatile("cp.async.commit_group;" ::: "memory")
#define CP_WAIT1()  asm volatile("cp.async.wait_group 1;" ::: "memory")

__device__ __forceinline__ void bsplit(float v, unsigned short& h, unsigned short& l) {
    __nv_bfloat16 bh = __float2bfloat16(v);
    __nv_bfloat16 bl = __float2bfloat16(v - __bfloat162float(bh));
    h = __bfloat16_as_ushort(bh);
    l = __bfloat16_as_ushort(bl);
}
__device__ __forceinline__ void hl_pack(float x, float y, uint32_t& hr, uint32_t& lr) {
    __nv_bfloat16 xh = __float2bfloat16(x);
    __nv_bfloat16 yh = __float2bfloat16(y);
    __nv_bfloat16 xl = __float2bfloat16(x - __bfloat162float(xh));
    __nv_bfloat16 yl = __float2bfloat16(y - __bfloat162float(yh));
    hr = (uint32_t)__bfloat16_as_ushort(xh) | ((uint32_t)__bfloat16_as_ushort(yh) << 16);
    lr = (uint32_t)__bfloat16_as_ushort(xl) | ((uint32_t)__bfloat16_as_ushort(yl) << 16);
}

// ======================= prep kernels =======================
__global__ void __launch_bounds__(256) split2(
    const float* __restrict__ src, unsigned short* __restrict__ h,
    unsigned short* __restrict__ l, int n)
{
    int i = blockIdx.x * 256 + threadIdx.x;
    if (i < n) bsplit(src[i], h[i], l[i]);
}

__global__ void __launch_bounds__(256) transpose_split(
    const float* __restrict__ W, unsigned short* __restrict__ Th,
    unsigned short* __restrict__ Tl, int K, int N)
{
    __shared__ float t[32][33];
    int n0 = blockIdx.x * 32, k0 = blockIdx.y * 32;
    int tx = threadIdx.x & 31, ty = threadIdx.x >> 5;
    #pragma unroll
    for (int i = 0; i < 4; i++) {
        int k = k0 + ty + i * 8, n = n0 + tx;
        t[ty + i * 8][tx] = (n < N) ? W[(size_t)k * N + n] : 0.f;
    }
    __syncthreads();
    #pragma unroll
    for (int i = 0; i < 4; i++) {
        int n = n0 + ty + i * 8, k = k0 + tx;
        bsplit(t[tx][ty + i * 8], Th[(size_t)n * K + k], Tl[(size_t)n * K + k]);
    }
}

// === HMMA split GEMM v5: 3-stage ring, 1 barrier/chunk, XOR swizzle 64B ===
// smem row = 64B (32 bf16), swizzle: chunk16B ^= (row>>1)&3. Tensor 8KB,
// stage 32KB, 3 stages = 96KB -> 2 CTAs/SM.
#define TEN_B    8192
#define STAGE_B  32768
#define GEMM_SMEM (3 * STAGE_B)   // 98304

__global__ void __launch_bounds__(256, 2) gemm_mma(
    const unsigned short* __restrict__ Ahp, const unsigned short* __restrict__ Alp, int lda,
    const unsigned short* __restrict__ Bhp, const unsigned short* __restrict__ Blp, int ldb,
    float* __restrict__ C, int ldc, int N, int K, int ntx, int ntiles)
{
    extern __shared__ unsigned short smus[];
    const uint32_t sbase = smem_u32(smus);
    const int tid  = threadIdx.x;
    const int lane = tid & 31;
    const int wid  = tid >> 5;
    const int wm   = wid & 1;        // 0..1 m
    const int wn   = wid >> 1;       // 0..3 n
    const int NC   = K >> 5;

    // per-thread swizzle constants
    const uint32_t r2 = (uint32_t)((lane >> 1) & 3);
    // A: row = wm*64 + (lane&15) (+ mf*16); chunk = ks*2 + (lane>>4)
    const uint32_t a_rowoff = (uint32_t)((wm * 64 + (lane & 15)) * 64);
    const uint32_t axk0 = (((uint32_t)(lane >> 4) + 0u) ^ r2) * 16u;
    const uint32_t axk1 = (((uint32_t)(lane >> 4) + 2u) ^ r2) * 16u;
    // B: row = wn*32 + (lane>>4)*8 + (lane&7) (+ np*16); chunk = ks*2 + ((lane>>3)&1)
    const uint32_t b_rowoff = (uint32_t)((wn * 32 + ((lane >> 4) * 8) + (lane & 7)) * 64);
    const uint32_t bxk0 = (((uint32_t)((lane >> 3) & 1) + 0u) ^ r2) * 16u;
    const uint32_t bxk1 = (((uint32_t)((lane >> 3) & 1) + 2u) ^ r2) * 16u;

    for (int tile = blockIdx.x; tile < ntiles; tile += gridDim.x) {
        const int row0 = (tile / ntx) * 128;
        const int col0 = (tile % ntx) * 128;
        const unsigned short* bases[4] = { Ahp, Alp, Bhp, Blp };
        const int ldv[4] = { lda, lda, ldb, ldb };
        const int rbv[4] = { row0, row0, col0, col0 };

        float acc[4][4][4];
        #pragma unroll
        for (int i = 0; i < 4; i++)
            #pragma unroll
            for (int j = 0; j < 4; j++)
                #pragma unroll
                for (int q = 0; q < 4; q++) acc[i][j][q] = 0.f;

        auto issue_chunk = [&](int c, int s) {
            const int k0 = c << 5;
            const uint32_t sb = sbase + (uint32_t)s * STAGE_B;
            #pragma unroll
            for (int t = 0; t < 4; t++)
                #pragma unroll
                for (int i = 0; i < 2; i++) {
                    int w = tid + i * 256;          // 0..511
                    int r = w >> 2, c16 = w & 3;
                    uint32_t phys = (uint32_t)(c16 ^ ((r >> 1) & 3));
                    cp16(sb + (uint32_t)(t * TEN_B + r * 64) + phys * 16u,
                         bases[t] + (size_t)(rbv[t] + r) * ldv[t] + k0 + c16 * 8);
                }
            CP_COMMIT();
        };

        issue_chunk(0, 0);

        for (int c = 0; c < NC; c++) {
            const int s = c % 3;
            if (c + 1 < NC) issue_chunk(c + 1, (c + 1) % 3);
            else            CP_COMMIT();          // keep group count uniform
            CP_WAIT1();                           // own chunk-c copies done
            __syncthreads();                      // ALL threads' copies visible

            const uint32_t st = sbase + (uint32_t)s * STAGE_B;
            #pragma unroll
            for (int ks = 0; ks < 2; ks++) {
                const uint32_t axk = ks ? axk1 : axk0;
                const uint32_t bxk = ks ? bxk1 : bxk0;
                uint32_t Ah[4][4], Al[4][4], Bh[4][2], Bl[4][2];
                #pragma unroll
                for (int mf = 0; mf < 4; mf++) {
                    ldm_x4(Ah[mf], st + 0     + a_rowoff + (uint32_t)(mf * 1024) + axk);
                    ldm_x4(Al[mf], st + TEN_B + a_rowoff + (uint32_t)(mf * 1024) + axk);
                }
                #pragma unroll
                for (int np = 0; np < 2; np++) {
                    uint32_t rh[4], rl[4];
                    ldm_x4(rh, st + 2 * TEN_B + b_rowoff + (uint32_t)(np * 1024) + bxk);
                    ldm_x4(rl, st + 3 * TEN_B + b_rowoff + (uint32_t)(np * 1024) + bxk);
                    Bh[np * 2][0] = rh[0]; Bh[np * 2][1] = rh[1];
                    Bh[np * 2 + 1][0] = rh[2]; Bh[np * 2 + 1][1] = rh[3];
                    Bl[np * 2][0] = rl[0]; Bl[np * 2][1] = rl[1];
                    Bl[np * 2 + 1][0] = rl[2]; Bl[np * 2 + 1][1] = rl[3];
                }
                #pragma unroll
                for (int mf = 0; mf < 4; mf++)
                    #pragma unroll
                    for (int nf = 0; nf < 4; nf++) {
                        mma16816(acc[mf][nf], Ah[mf], Bh[nf]);
                        mma16816(acc[mf][nf], Ah[mf], Bl[nf]);
                        mma16816(acc[mf][nf], Al[mf], Bh[nf]);
                    }
            }
        }

        #pragma unroll
        for (int mf = 0; mf < 4; mf++) {
            int r0 = row0 + wm * 64 + mf * 16 + (lane >> 2);
            #pragma unroll
            for (int nf = 0; nf < 4; nf++) {
                int c0 = col0 + wn * 32 + nf * 8 + (lane & 3) * 2;
                if (c0 < N) {
                    C[(size_t)r0 * ldc + c0] = acc[mf][nf][0];
                    C[(size_t)(r0 + 8) * ldc + c0] = acc[mf][nf][2];
                }
                if (c0 + 1 < N) {
                    C[(size_t)r0 * ldc + c0 + 1] = acc[mf][nf][1];
                    C[(size_t)(r0 + 8) * ldc + c0 + 1] = acc[mf][nf][3];
                }
            }
        }
        __syncthreads();    // tile boundary: protect stage 0 reuse (WAR)
    }
}

// ======================= rmsnorm =======================
__global__ void __launch_bounds__(256) rmsnorm_kernel(
    float* __restrict__ data, const float* __restrict__ w, int W, int ld)
{
    const int row = blockIdx.x;
    float* p = data + (size_t)row * ld;
    float ss = 0.f;
    for (int c = threadIdx.x; c < W; c += 256) { float v = p[c]; ss += v * v; }
    __shared__ float red[256];
    red[threadIdx.x] = ss;
    __syncthreads();
    #pragma unroll
    for (int s = 128; s > 0; s >>= 1) {
        if (threadIdx.x < s) red[threadIdx.x] += red[threadIdx.x + s];
        __syncthreads();
    }
    float scale = rsqrtf(red[0] / (float)W + 1e-6f);
    for (int c = threadIdx.x; c < W; c += 256) p[c] = w[c] * (p[c] * scale);
}

// ======================= rope + per-head bf16 hi/lo layout =================
__global__ void __launch_bounds__(256) build_qk(const float* __restrict__ freqs)
{
    const int s = blockIdx.x;
    const int tid = threadIdx.x;
    __shared__ float cs[32], sn[32];
    if (tid < 32) {
        cs[tid] = freqs[(s * 32 + tid) * 2 + 0];
        sn[tid] = freqs[(s * 32 + tid) * 2 + 1];
    }
    __syncthreads();

    const float* qrow = g_q + (size_t)s * NQ;
    for (int idx = tid; idx < NQ; idx += 256) {
        int hh = idx / QHDIM, d = idx % QHDIM;
        float val;
        if (d < ROPED) {
            int j = d >> 1;
            float a = qrow[hh * QHDIM + NOPED + 2 * j];
            float b = qrow[hh * QHDIM + NOPED + 2 * j + 1];
            val = (d & 1) ? (a * sn[j] + b * cs[j]) : (a * cs[j] - b * sn[j]);
        } else {
            val = qrow[hh * QHDIM + (d - ROPED)];
        }
        size_t off = ((size_t)hh * SEQ + s) * QHDIM + d;
        bsplit(val, g_Qbh[off], g_Qbl[off]);
    }

    const float* kperow = g_ckv + (size_t)s * KVW + KVLORA;
    const float* kvrow  = g_kv  + (size_t)s * NKV;
    for (int idx = tid; idx < NQ; idx += 256) {
        int hh = idx / QHDIM, d = idx % QHDIM;
        float val;
        if (d < ROPED) {
            int j = d >> 1;
            float a = kperow[2 * j], b = kperow[2 * j + 1];
            val = (d & 1) ? (a * sn[j] + b * cs[j]) : (a * cs[j] - b * sn[j]);
        } else {
            val = kvrow[hh * KVROW + (d - ROPED)];
        }
        size_t off = ((size_t)hh * SEQ + s) * QHDIM + d;
        bsplit(val, g_Kbh[off], g_Kbl[off]);
    }

    for (int idx = tid; idx < NHEAD * VD; idx += 256) {
        int hh = idx / VD, d = idx % VD;
        float v = kvrow[hh * KVROW + NOPED + d];
        size_t off = ((size_t)hh * SEQ + s) * VD + d;
        bsplit(v, g_Vbh[off], g_Vbl[off]);
    }
}

// ======================= HMMA flash attention (unchanged R9) ==============
#define FL_SMEM_BYTES 188416

__global__ void __launch_bounds__(256) flash_mma(
    const int* __restrict__ mask, float* __restrict__ ao)
{
    extern __shared__ unsigned short fsm[];
    const uint32_t sb = smem_u32(fsm);
    const int tid  = threadIdx.x;
    const int lane = tid & 31;
    const int wq   = tid >> 5;
    const int qb   = blockIdx.x;
    const int h    = blockIdx.y;
    const int g    = lane >> 2;
    const int t    = lane & 3;
    const int bq   = lane >> 3;
    const int br   = lane & 7;
    const float scale = 0.088388347648318447f;

    unsigned short* Qh_s = fsm;
    unsigned short* Ql_s = fsm + 25600;
    unsigned short* Kh_s = fsm + 51200;
    unsigned short* Kl_s = fsm + 64000;
    unsigned short* Vh_s = fsm + 76800;
    unsigned short* Vl_s = fsm + 85504;

    const uint32_t aH = sb + (uint32_t)((wq * 16 + (lane & 15)) * 400 + (lane >> 4) * 16);
    const uint32_t aL = aH + 51200;
    const uint32_t kH = sb + 102400 + (uint32_t)(((bq >> 1) * 8 + br) * 400 + (bq & 1) * 16);
    const uint32_t kL = kH + 25600;
    const uint32_t vH = sb + 153600 + (uint32_t)(((bq & 1) * 8 + br) * 272 + (bq >> 1) * 16);
    const uint32_t vL = vH + 17408;

    const size_t qgo = ((size_t)h * SEQ + (size_t)qb * 128) * QHDIM;
    for (int i = tid; i < 128 * 24; i += 256) {
        int r = i / 24, c = i % 24;
        *(uint4*)(Qh_s + r * 200 + c * 8) = *(const uint4*)(g_Qbh + qgo + (size_t)r * QHDIM + c * 8);
        *(uint4*)(Ql_s + r * 200 + c * 8) = *(const uint4*)(g_Qbl + qgo + (size_t)r * QHDIM + c * 8);
    }

    float o[16][4];
    #pragma unroll
    for (int i = 0; i < 16; i++)
        #pragma unroll
        for (int j = 0; j < 4; j++) o[i][j] = 0.f;
    float mr0 = NEG_BIG, mr1 = NEG_BIG, l0 = 0.f, l1 = 0.f;

    const int row0g = qb * 128 + wq * 16 + g;

    for (int kb = 0; kb < SEQ / 64; kb++) {
        __syncthreads();
        const size_t kgo = ((size_t)h * SEQ + (size_t)kb * 64) * QHDIM;
        for (int i = tid; i < 64 * 24; i += 256) {
            int r = i / 24, c = i % 24;
            *(uint4*)(Kh_s + r * 200 + c * 8) = *(const uint4*)(g_Kbh + kgo + (size_t)r * QHDIM + c * 8);
            *(uint4*)(Kl_s + r * 200 + c * 8) = *(const uint4*)(g_Kbl + kgo + (size_t)r * QHDIM + c * 8);
        }
        const size_t vgo = ((size_t)h * SEQ + (size_t)kb * 64) * VD;
        for (int i = tid; i < 64 * 16; i += 256) {
            int r = i / 16, c = i % 16;
            *(uint4*)(Vh_s + r * 136 + c * 8) = *(const uint4*)(g_Vbh + vgo + (size_t)r * VD + c * 8);
            *(uint4*)(Vl_s + r * 136 + c * 8) = *(const uint4*)(g_Vbl + vgo + (size_t)r * VD + c * 8);
        }
        __syncthreads();

        float s[8][4];
        #pragma unroll
        for (int f = 0; f < 8; f++)
            #pragma unroll
            for (int e = 0; e < 4; e++) s[f][e] = 0.f;

        #pragma unroll
        for (int kk = 0; kk < 12; kk++) {
            uint32_t ah[4], al[4];
            ldm_x4(ah, aH + kk * 32);
            ldm_x4(al, aL + kk * 32);
            #pragma unroll
            for (int np = 0; np < 4; np++) {
                uint32_t bh[4], bl[4];
                ldm_x4(bh, kH + np * (16 * 400) + kk * 32);
                ldm_x4(bl, kL + np * (16 * 400) + kk * 32);
                mma16816(s[2 * np],     ah, bh);
                mma16816(s[2 * np],     ah, bl);
                mma16816(s[2 * np],     al, bh);
                mma16816(s[2 * np + 1], ah, bh + 2);
                mma16816(s[2 * np + 1], ah, bl + 2);
                mma16816(s[2 * np + 1], al, bh + 2);
            }
        }

        #pragma unroll
        for (int f = 0; f < 8; f++)
            #pragma unroll
            for (int e = 0; e < 4; e++) s[f][e] *= scale;

        const int colbase = 150 + kb * 64;
        #pragma unroll
        for (int f = 0; f < 8; f++) {
            int col = colbase + f * 8 + 2 * t;
            int2 m0v = *(const int2*)(mask + (size_t)row0g * MASKW + col);
            int2 m1v = *(const int2*)(mask + (size_t)(row0g + 8) * MASKW + col);
            if (m0v.x == 1) s[f][0] = NEG_BIG;
            if (m0v.y == 1) s[f][1] = NEG_BIG;
            if (m1v.x == 1) s[f][2] = NEG_BIG;
            if (m1v.y == 1) s[f][3] = NEG_BIG;
        }

        float m0 = NEG_BIG, m1 = NEG_BIG;
        #pragma unroll
        for (int f = 0; f < 8; f++) {
            m0 = fmaxf(m0, fmaxf(s[f][0], s[f][1]));
            m1 = fmaxf(m1, fmaxf(s[f][2], s[f][3]));
        }
        m0 = fmaxf(m0, __shfl_xor_sync(0xffffffffu, m0, 1));
        m0 = fmaxf(m0, __shfl_xor_sync(0xffffffffu, m0, 2));
        m1 = fmaxf(m1, __shfl_xor_sync(0xffffffffu, m1, 1));
        m1 = fmaxf(m1, __shfl_xor_sync(0xffffffffu, m1, 2));
        float nm0 = fmaxf(mr0, m0), nm1 = fmaxf(mr1, m1);
        float al0 = __expf(mr0 - nm0), al1 = __expf(mr1 - nm1);
        mr0 = nm0; mr1 = nm1;

        float sum0 = 0.f, sum1 = 0.f;
        #pragma unroll
        for (int f = 0; f < 8; f++) {
            s[f][0] = __expf(s[f][0] - nm0);
            s[f][1] = __expf(s[f][1] - nm0);
            s[f][2] = __expf(s[f][2] - nm1);
            s[f][3] = __expf(s[f][3] - nm1);
            sum0 += s[f][0] + s[f][1];
            sum1 += s[f][2] + s[f][3];
        }
        sum0 += __shfl_xor_sync(0xffffffffu, sum0, 1);
        sum0 += __shfl_xor_sync(0xffffffffu, sum0, 2);
        sum1 += __shfl_xor_sync(0xffffffffu, sum1, 1);
        sum1 += __shfl_xor_sync(0xffffffffu, sum1, 2);
        l0 = l0 * al0 + sum0;
        l1 = l1 * al1 + sum1;

        #pragma unroll
        for (int nf = 0; nf < 16; nf++) {
            o[nf][0] *= al0; o[nf][1] *= al0;
            o[nf][2] *= al1; o[nf][3] *= al1;
        }

        uint32_t pah[4][4], pal[4][4];
        #pragma unroll
        for (int kk2 = 0; kk2 < 4; kk2++) {
            hl_pack(s[2 * kk2][0],     s[2 * kk2][1],     pah[kk2][0], pal[kk2][0]);
            hl_pack(s[2 * kk2][2],     s[2 * kk2][3],     pah[kk2][1], pal[kk2][1]);
            hl_pack(s[2 * kk2 + 1][0], s[2 * kk2 + 1][1], pah[kk2][2], pal[kk2][2]);
            hl_pack(s[2 * kk2 + 1][2], s[2 * kk2 + 1][3], pah[kk2][3], pal[kk2][3]);
        }

        #pragma unroll
        for (int kk2 = 0; kk2 < 4; kk2++) {
            #pragma unroll
            for (int jj = 0; jj < 8; jj++) {
                uint32_t vh4[4], vl4[4];
                ldm_x4_t(vh4, vH + kk2 * (16 * 272) + jj * 32);
                ldm_x4_t(vl4, vL + kk2 * (16 * 272) + jj * 32);
                mma16816(o[2 * jj],     pah[kk2], vh4);
                mma16816(o[2 * jj],     pah[kk2], vl4);
                mma16816(o[2 * jj],     pal[kk2], vh4);
                mma16816(o[2 * jj + 1], pah[kk2], vh4 + 2);
                mma16816(o[2 * jj + 1], pah[kk2], vl4 + 2);
                mma16816(o[2 * jj + 1], pal[kk2], vh4 + 2);
            }
        }
    }

    const float inv0 = 1.f / l0, inv1 = 1.f / l1;
    #pragma unroll
    for (int nf = 0; nf < 16; nf++) {
        int col = h * VD + nf * 8 + 2 * t;
        *(float2*)(ao + (size_t)row0g * DM + col) =
            make_float2(o[nf][0] * inv0, o[nf][1] * inv0);
        *(float2*)(ao + (size_t)(row0g + 8) * DM + col) =
            make_float2(o[nf][2] * inv1, o[nf][3] * inv1);
    }
}

// ---------------------------------------------------------------------------
static inline int mini(int a, int b) { return a < b ? a : b; }

extern "C" void kernel_launch(void* const* d_in, const int* in_sizes, int n_in,
                              void* d_out, int out_size)
{
    const float* x     = (const float*)d_in[0];
    const int*   mask  = (const int*)  d_in[1];
    const float* freqs = (const float*)d_in[2];
    const float* Wqa   = (const float*)d_in[3];
    const float* qln   = (const float*)d_in[4];
    const float* Wqb   = (const float*)d_in[5];
    const float* Wkva  = (const float*)d_in[6];
    const float* kvln  = (const float*)d_in[7];
    const float* Wkvb  = (const float*)d_in[8];
    const float* Wo    = (const float*)d_in[9];
    float* out = (float*)d_out;

    float *qlat, *ckv, *kv, *ao, *qbuf;
    cudaGetSymbolAddress((void**)&qlat, g_qlat);
    cudaGetSymbolAddress((void**)&ckv,  g_ckv);
    cudaGetSymbolAddress((void**)&kv,   g_kv);
    cudaGetSymbolAddress((void**)&ao,   g_ao);
    cudaGetSymbolAddress((void**)&qbuf, g_q);

    unsigned short *xh,*xl,*qlh,*qll,*ckh,*ckl,*aoh,*aol;
    unsigned short *WqaTh,*WqaTl,*WkvaTh,*WkvaTl,*WqbTh,*WqbTl,*WkvbTh,*WkvbTl,*WoTh,*WoTl;
    cudaGetSymbolAddress((void**)&xh,  g_xh);   cudaGetSymbolAddress((void**)&xl,  g_xl);
    cudaGetSymbolAddress((void**)&qlh, g_qlh);  cudaGetSymbolAddress((void**)&qll, g_qll);
    cudaGetSymbolAddress((void**)&ckh, g_ckh);  cudaGetSymbolAddress((void**)&ckl, g_ckl);
    cudaGetSymbolAddress((void**)&aoh, g_aoh);  cudaGetSymbolAddress((void**)&aol, g_aol);
    cudaGetSymbolAddress((void**)&WqaTh, g_WqaTh);   cudaGetSymbolAddress((void**)&WqaTl, g_WqaTl);
    cudaGetSymbolAddress((void**)&WkvaTh, g_WkvaTh); cudaGetSymbolAddress((void**)&WkvaTl, g_WkvaTl);
    cudaGetSymbolAddress((void**)&WqbTh, g_WqbTh);   cudaGetSymbolAddress((void**)&WqbTl, g_WqbTl);
    cudaGetSymbolAddress((void**)&WkvbTh, g_WkvbTh); cudaGetSymbolAddress((void**)&WkvbTl, g_WkvbTl);
    cudaGetSymbolAddress((void**)&WoTh, g_WoTh);     cudaGetSymbolAddress((void**)&WoTl, g_WoTl);

    cudaFuncSetAttribute(gemm_mma, cudaFuncAttributeMaxDynamicSharedMemorySize, GEMM_SMEM);
    cudaFuncSetAttribute(flash_mma, cudaFuncAttributeMaxDynamicSharedMemorySize, FL_SMEM_BYTES);
    dim3 blk(256);

    const int t1 = (QLORA / 128) * (SEQ / 128);   // 192
    const int t2 = (KVWP  / 128) * (SEQ / 128);   // 80
    const int t3 = (NQ    / 128) * (SEQ / 128);   // 384
    const int t4 = (NKV   / 128) * (SEQ / 128);   // 512
    const int t5 = (DM    / 128) * (SEQ / 128);   // 256
    const int PG = 296;                            // 2 x 148 persistent CTAs

    // my launch idx:                                                       // idx
    split2<<<(SEQ * DM + 255) / 256, blk>>>(x, xh, xl, SEQ * DM);           // 0
    transpose_split<<<dim3(QLORA / 32, DM / 32), blk>>>(Wqa, WqaTh, WqaTl, DM, QLORA); // 1
    transpose_split<<<dim3(KVWP / 32, DM / 32), blk>>>(Wkva, WkvaTh, WkvaTl, DM, KVW); // 2
    gemm_mma<<<mini(t1, PG), blk, GEMM_SMEM>>>(                             // 3 <- profiled
        xh, xl, DM, WqaTh, WqaTl, DM, qlat, QLORA, QLORA, DM, QLORA / 128, t1);
    gemm_mma<<<mini(t2, PG), blk, GEMM_SMEM>>>(
        xh, xl, DM, WkvaTh, WkvaTl, DM, ckv, KVW, KVW, DM, KVWP / 128, t2);
    rmsnorm_kernel<<<SEQ, 256>>>(qlat, qln, QLORA, QLORA);
    rmsnorm_kernel<<<SEQ, 256>>>(ckv, kvln, KVLORA, KVW);
    split2<<<(SEQ * QLORA + 255) / 256, blk>>>(qlat, qlh, qll, SEQ * QLORA);
    split2<<<(SEQ * KVW + 255) / 256, blk>>>(ckv, ckh, ckl, SEQ * KVW);
    transpose_split<<<dim3(NQ / 32, QLORA / 32), blk>>>(Wqb, WqbTh, WqbTl, QLORA, NQ);
    transpose_split<<<dim3(NKV / 32, KVLORA / 32), blk>>>(Wkvb, WkvbTh, WkvbTl, KVLORA, NKV);
    gemm_mma<<<mini(t3, PG), blk, GEMM_SMEM>>>(
        qlh, qll, QLORA, WqbTh, WqbTl, QLORA, qbuf, NQ, NQ, QLORA, NQ / 128, t3);
    gemm_mma<<<mini(t4, PG), blk, GEMM_SMEM>>>(
        ckh, ckl, KVW, WkvbTh, WkvbTl, KVLORA, kv, NKV, NKV, KVLORA, NKV / 128, t4);

    build_qk<<<SEQ, 256>>>(freqs);
    flash_mma<<<dim3(SEQ / 128, NHEAD), blk, FL_SMEM_BYTES>>>(mask, ao);

    transpose_split<<<dim3(DM / 32, DM / 32), blk>>>(Wo, WoTh, WoTl, DM, DM);
    split2<<<(SEQ * DM + 255) / 256, blk>>>(ao, aoh, aol, SEQ * DM);
    gemm_mma<<<mini(t5, PG), blk, GEMM_SMEM>>>(
        aoh, aol, DM, WoTh, WoTl, DM, out, DM, DM, DM, DM / 128, t5);
}